// round 2
// baseline (speedup 1.0000x reference)
#include <cuda_runtime.h>
#include <math.h>

#define BATCH 4
#define NSEQ 2048
#define CDIM 1024
#define HNUM 16
#define HD 64
#define C3 3072

// Scratch (device globals: allocation-free contract)
__device__ float g_qkv[(size_t)BATCH * NSEQ * C3];    // [B,N,3C]
__device__ float g_attn[(size_t)BATCH * NSEQ * CDIM]; // [B,N,C]

// ---------------------------------------------------------------------------
// NT SGEMM: C[m,n] = sum_k A[m,k] * W[n,k] (+ bias[n])
// BM=BN=64, BK=32, 256 threads, 4x4 per-thread tile, transposed smem operands.
// ---------------------------------------------------------------------------
__global__ void __launch_bounds__(256) gemm_nt_kernel(
    const float* __restrict__ A, const float* __restrict__ W,
    const float* __restrict__ bias, float* __restrict__ C,
    int M, int N, int K)
{
    __shared__ float As[32][68];
    __shared__ float Ws[32][68];
    const int t = threadIdx.x;
    const int ty = t >> 4, tx = t & 15;
    const int m0 = blockIdx.y << 6, n0 = blockIdx.x << 6;

    float acc[4][4] = {};

    for (int k0 = 0; k0 < K; k0 += 32) {
        __syncthreads();
#pragma unroll
        for (int i = 0; i < 2; i++) {
            int idx = t + (i << 8);            // 0..511
            int r  = idx >> 3;                 // 0..63
            int c4 = (idx & 7) << 2;           // 0,4,...,28
            float4 va = *(const float4*)(A + (size_t)(m0 + r) * K + k0 + c4);
            As[c4 + 0][r] = va.x; As[c4 + 1][r] = va.y;
            As[c4 + 2][r] = va.z; As[c4 + 3][r] = va.w;
            float4 vw = *(const float4*)(W + (size_t)(n0 + r) * K + k0 + c4);
            Ws[c4 + 0][r] = vw.x; Ws[c4 + 1][r] = vw.y;
            Ws[c4 + 2][r] = vw.z; Ws[c4 + 3][r] = vw.w;
        }
        __syncthreads();
#pragma unroll
        for (int kk = 0; kk < 32; kk++) {
            float4 a = *(float4*)&As[kk][ty << 2];
            float4 b = *(float4*)&Ws[kk][tx << 2];
            float ar[4] = {a.x, a.y, a.z, a.w};
            float br[4] = {b.x, b.y, b.z, b.w};
#pragma unroll
            for (int i = 0; i < 4; i++)
#pragma unroll
                for (int j = 0; j < 4; j++)
                    acc[i][j] += ar[i] * br[j];
        }
    }

#pragma unroll
    for (int i = 0; i < 4; i++) {
        int m = m0 + (ty << 2) + i;
        int n = n0 + (tx << 2);
        float4 r;
        r.x = acc[i][0]; r.y = acc[i][1]; r.z = acc[i][2]; r.w = acc[i][3];
        if (bias) {
            r.x += bias[n + 0]; r.y += bias[n + 1];
            r.z += bias[n + 2]; r.w += bias[n + 3];
        }
        *(float4*)(C + (size_t)m * N + n) = r;
    }
}

// ---------------------------------------------------------------------------
// RMSNorm + RoPE on q and k, in place in g_qkv.
// Block = one (b,n); warp = one head; lane owns elems (e, e+32) so
// rotate_half pairs are register-local.
// ---------------------------------------------------------------------------
__global__ void __launch_bounds__(512) rmsrope_kernel(
    float* __restrict__ qkv,
    const float* __restrict__ rc, const float* __restrict__ rs,
    const float* __restrict__ qw, const float* __restrict__ kw)
{
    const int bn = blockIdx.x;
    const int n = bn & (NSEQ - 1);
    const int h = threadIdx.x >> 5;
    const int lane = threadIdx.x & 31;

    float* q = qkv + (size_t)bn * C3 + h * HD;
    float* k = q + CDIM;
    const int e1 = lane, e2 = lane + 32;

    const float c1 = rc[n * HD + e1], c2 = rc[n * HD + e2];
    const float s1 = rs[n * HD + e1], s2 = rs[n * HD + e2];

    // q
    {
        float a = q[e1], b = q[e2];
        float ss = a * a + b * b;
#pragma unroll
        for (int m = 16; m > 0; m >>= 1) ss += __shfl_xor_sync(0xffffffffu, ss, m);
        float inv = rsqrtf(ss * (1.0f / HD) + 1e-6f);
        a *= inv * qw[e1];
        b *= inv * qw[e2];
        q[e1] = a * c1 - b * s1;   // out = x*cos + (-x2)*sin (first half)
        q[e2] = b * c2 + a * s2;   // out = x*cos + ( x1)*sin (second half)
    }
    // k
    {
        float a = k[e1], b = k[e2];
        float ss = a * a + b * b;
#pragma unroll
        for (int m = 16; m > 0; m >>= 1) ss += __shfl_xor_sync(0xffffffffu, ss, m);
        float inv = rsqrtf(ss * (1.0f / HD) + 1e-6f);
        a *= inv * kw[e1];
        b *= inv * kw[e2];
        k[e1] = a * c1 - b * s1;
        k[e2] = b * c2 + a * s2;
    }
}

// ---------------------------------------------------------------------------
// Flash attention fp32. Block = (qblock 64 rows, head, batch), 256 threads.
// Online softmax; 64-key tiles; K transposed in smem, V natural, P staged
// through smem for the PV GEMM. Dynamic smem: 4 * 64 * 68 * 4 = 69632 B.
// ---------------------------------------------------------------------------
__global__ void __launch_bounds__(256) attn_kernel(
    const float* __restrict__ qkv, float* __restrict__ out)
{
    extern __shared__ float sm[];
    float* Qs = sm;                 // [d][r]  stride 68
    float* Ks = Qs + 64 * 68;       // [d][c]
    float* Ps = Ks + 64 * 68;       // [c][r]
    float* Vs = Ps + 64 * 68;       // [c][d]

    const int qb = blockIdx.x, h = blockIdx.y, b = blockIdx.z;
    const int t = threadIdx.x;
    const int ty = t >> 4, tx = t & 15;

    const size_t base = (size_t)b * NSEQ * C3 + h * HD;

    // Load Q tile transposed, pre-scaled by hd^-0.5 = 0.125
#pragma unroll
    for (int i = 0; i < 4; i++) {
        int idx = t + (i << 8);
        int r = idx >> 4, d4 = (idx & 15) << 2;
        float4 v = *(const float4*)(qkv + base + (size_t)(qb * 64 + r) * C3 + d4);
        Qs[(d4 + 0) * 68 + r] = v.x * 0.125f;
        Qs[(d4 + 1) * 68 + r] = v.y * 0.125f;
        Qs[(d4 + 2) * 68 + r] = v.z * 0.125f;
        Qs[(d4 + 3) * 68 + r] = v.w * 0.125f;
    }

    float o[4][4] = {};
    float mrow[4] = {-1e30f, -1e30f, -1e30f, -1e30f};
    float lrow[4] = {};

    for (int kt = 0; kt < NSEQ / 64; kt++) {
        __syncthreads();
        // Load K (transposed) and V (natural) tiles
#pragma unroll
        for (int i = 0; i < 4; i++) {
            int idx = t + (i << 8);
            int c = idx >> 4, d4 = (idx & 15) << 2;
            size_t rowoff = base + (size_t)(kt * 64 + c) * C3;
            float4 kv = *(const float4*)(qkv + rowoff + CDIM + d4);
            Ks[(d4 + 0) * 68 + c] = kv.x; Ks[(d4 + 1) * 68 + c] = kv.y;
            Ks[(d4 + 2) * 68 + c] = kv.z; Ks[(d4 + 3) * 68 + c] = kv.w;
            float4 vv = *(const float4*)(qkv + rowoff + 2 * CDIM + d4);
            *(float4*)&Vs[c * 68 + d4] = vv;
        }
        __syncthreads();

        // S = (Q*scale) K^T  (4x4 per thread)
        float s[4][4] = {};
#pragma unroll
        for (int d = 0; d < 64; d++) {
            float4 a = *(float4*)&Qs[d * 68 + (ty << 2)];
            float4 bb = *(float4*)&Ks[d * 68 + (tx << 2)];
            float ar[4] = {a.x, a.y, a.z, a.w};
            float br[4] = {bb.x, bb.y, bb.z, bb.w};
#pragma unroll
            for (int i = 0; i < 4; i++)
#pragma unroll
                for (int j = 0; j < 4; j++)
                    s[i][j] += ar[i] * br[j];
        }

        // Online softmax (row stats reduced over the 16 tx lanes)
#pragma unroll
        for (int i = 0; i < 4; i++) {
            float mx = fmaxf(fmaxf(s[i][0], s[i][1]), fmaxf(s[i][2], s[i][3]));
#pragma unroll
            for (int msk = 8; msk > 0; msk >>= 1)
                mx = fmaxf(mx, __shfl_xor_sync(0xffffffffu, mx, msk));
            float mn = fmaxf(mrow[i], mx);
            float alpha = __expf(mrow[i] - mn);
            mrow[i] = mn;
            float rsum = 0.0f;
#pragma unroll
            for (int j = 0; j < 4; j++) {
                float p = __expf(s[i][j] - mn);
                s[i][j] = p;
                rsum += p;
            }
#pragma unroll
            for (int msk = 8; msk > 0; msk >>= 1)
                rsum += __shfl_xor_sync(0xffffffffu, rsum, msk);
            lrow[i] = lrow[i] * alpha + rsum;
#pragma unroll
            for (int j = 0; j < 4; j++) o[i][j] *= alpha;
#pragma unroll
            for (int j = 0; j < 4; j++)
                Ps[((tx << 2) + j) * 68 + (ty << 2) + i] = s[i][j];
        }
        __syncthreads();

        // O += P V
#pragma unroll
        for (int kk = 0; kk < 64; kk++) {
            float4 p = *(float4*)&Ps[kk * 68 + (ty << 2)];
            float4 v = *(float4*)&Vs[kk * 68 + (tx << 2)];
            float pr[4] = {p.x, p.y, p.z, p.w};
            float vr[4] = {v.x, v.y, v.z, v.w};
#pragma unroll
            for (int i = 0; i < 4; i++)
#pragma unroll
                for (int j = 0; j < 4; j++)
                    o[i][j] += pr[i] * vr[j];
        }
    }

    // Normalize and write to [B,N,C] layout
    const size_t obase = (size_t)b * NSEQ * CDIM + h * HD;
#pragma unroll
    for (int i = 0; i < 4; i++) {
        int r = qb * 64 + (ty << 2) + i;
        float invl = 1.0f / lrow[i];
        float4 w;
        w.x = o[i][0] * invl; w.y = o[i][1] * invl;
        w.z = o[i][2] * invl; w.w = o[i][3] * invl;
        *(float4*)(out + obase + (size_t)r * CDIM + (tx << 2)) = w;
    }
}

// ---------------------------------------------------------------------------
extern "C" void kernel_launch(void* const* d_in, const int* in_sizes, int n_in,
                              void* d_out, int out_size)
{
    const float* x     = (const float*)d_in[0];
    const float* rc    = (const float*)d_in[1];
    const float* rs    = (const float*)d_in[2];
    const float* wqkv  = (const float*)d_in[3];
    const float* wproj = (const float*)d_in[4];
    const float* bproj = (const float*)d_in[5];
    const float* qw    = (const float*)d_in[6];
    const float* kw    = (const float*)d_in[7];
    float* out = (float*)d_out;

    float *qkv = nullptr, *attn = nullptr;
    cudaGetSymbolAddress((void**)&qkv, g_qkv);
    cudaGetSymbolAddress((void**)&attn, g_attn);

    const int M = BATCH * NSEQ; // 8192

    // 1) QKV projection: [8192,1024] x [3072,1024]^T
    gemm_nt_kernel<<<dim3(C3 / 64, M / 64), 256>>>(x, wqkv, nullptr, qkv, M, C3, CDIM);

    // 2) RMSNorm + RoPE in place on q,k
    rmsrope_kernel<<<M, 512>>>(qkv, rc, rs, qw, kw);

    // 3) Flash attention
    cudaFuncSetAttribute(attn_kernel, cudaFuncAttributeMaxDynamicSharedMemorySize, 69632);
    attn_kernel<<<dim3(NSEQ / 64, HNUM, BATCH), 256, 69632>>>(qkv, attn);

    // 4) Output projection + bias
    gemm_nt_kernel<<<dim3(CDIM / 64, M / 64), 256>>>(attn, wproj, bproj, out, M, CDIM, CDIM);
}

// round 4
// speedup vs baseline: 1.5504x; 1.5504x over previous
#include <cuda_runtime.h>
#include <math.h>
#include <stdint.h>

#define BATCH 4
#define NSEQ 2048
#define CDIM 1024
#define HNUM 16
#define HD 64
#define C3 3072

// Scratch (device globals: allocation-free contract)
__device__ float g_qkv[(size_t)BATCH * NSEQ * C3];    // [B,N,3C]
__device__ float g_attn[(size_t)BATCH * NSEQ * CDIM]; // [B,N,C]

__device__ __forceinline__ uint32_t f2tf32(float x) {
    uint32_t r;
    asm("cvt.rna.tf32.f32 %0, %1;" : "=r"(r) : "f"(x));
    return r;
}

__device__ __forceinline__ void mma_tf32(float* d, const uint32_t* a, const uint32_t* b) {
    asm volatile(
        "mma.sync.aligned.m16n8k8.row.col.f32.tf32.tf32.f32 "
        "{%0,%1,%2,%3}, {%4,%5,%6,%7}, {%8,%9}, {%0,%1,%2,%3};"
        : "+f"(d[0]), "+f"(d[1]), "+f"(d[2]), "+f"(d[3])
        : "r"(a[0]), "r"(a[1]), "r"(a[2]), "r"(a[3]), "r"(b[0]), "r"(b[1]));
}

// ---------------------------------------------------------------------------
// TF32 NT GEMM: C[m,n] = sum_k A[m,k] * W[n,k] (+ bias[n])
// Block tile 128x128x32, 256 threads (8 warps, 2x4), warp tile 64x32.
// smem [row][k] stride 36: conflict-free float4 stores AND fragment loads.
// ---------------------------------------------------------------------------
__global__ void __launch_bounds__(256) gemm_tf32_nt(
    const float* __restrict__ A, const float* __restrict__ W,
    const float* __restrict__ bias, float* __restrict__ C,
    int M, int N, int K)
{
    __shared__ float As[128][36];
    __shared__ float Bs[128][36];

    const int t = threadIdx.x;
    const int wid = t >> 5, lane = t & 31;
    const int wm = wid & 1, wn = wid >> 1;       // warps: 2 in M, 4 in N
    const int r = lane >> 2, c = lane & 3;       // fragment indices
    const int m0 = blockIdx.y << 7, n0 = blockIdx.x << 7;

    float acc[4][4][4] = {};                     // [mi][ni][reg]

    for (int k0 = 0; k0 < K; k0 += 32) {
        __syncthreads();
#pragma unroll
        for (int i = 0; i < 4; i++) {
            int idx = t + (i << 8);              // 0..1023
            int row = idx >> 3;                  // 0..127
            int c4  = (idx & 7) << 2;            // 0,4,...,28
            float4 va = *(const float4*)(A + (size_t)(m0 + row) * K + k0 + c4);
            As[row][c4 + 0] = __uint_as_float(f2tf32(va.x));
            As[row][c4 + 1] = __uint_as_float(f2tf32(va.y));
            As[row][c4 + 2] = __uint_as_float(f2tf32(va.z));
            As[row][c4 + 3] = __uint_as_float(f2tf32(va.w));
            float4 vb = *(const float4*)(W + (size_t)(n0 + row) * K + k0 + c4);
            Bs[row][c4 + 0] = __uint_as_float(f2tf32(vb.x));
            Bs[row][c4 + 1] = __uint_as_float(f2tf32(vb.y));
            Bs[row][c4 + 2] = __uint_as_float(f2tf32(vb.z));
            Bs[row][c4 + 3] = __uint_as_float(f2tf32(vb.w));
        }
        __syncthreads();

#pragma unroll
        for (int kk = 0; kk < 32; kk += 8) {
            uint32_t af[4][4], bf[4][2];
#pragma unroll
            for (int mi = 0; mi < 4; mi++) {
                int mr = (wm << 6) + (mi << 4);
                af[mi][0] = __float_as_uint(As[mr + r    ][kk + c    ]);
                af[mi][1] = __float_as_uint(As[mr + r + 8][kk + c    ]);
                af[mi][2] = __float_as_uint(As[mr + r    ][kk + c + 4]);
                af[mi][3] = __float_as_uint(As[mr + r + 8][kk + c + 4]);
            }
#pragma unroll
            for (int ni = 0; ni < 4; ni++) {
                int nr = (wn << 5) + (ni << 3);
                bf[ni][0] = __float_as_uint(Bs[nr + r][kk + c    ]);
                bf[ni][1] = __float_as_uint(Bs[nr + r][kk + c + 4]);
            }
#pragma unroll
            for (int mi = 0; mi < 4; mi++)
#pragma unroll
                for (int ni = 0; ni < 4; ni++)
                    mma_tf32(acc[mi][ni], af[mi], bf[ni]);
        }
    }

    // Epilogue: c0=(r,2c) c1=(r,2c+1) c2=(r+8,2c) c3=(r+8,2c+1)
#pragma unroll
    for (int mi = 0; mi < 4; mi++) {
#pragma unroll
        for (int ni = 0; ni < 4; ni++) {
            int row = m0 + (wm << 6) + (mi << 4) + r;
            int col = n0 + (wn << 5) + (ni << 3) + (c << 1);
            float b0 = 0.0f, b1 = 0.0f;
            if (bias) { b0 = bias[col]; b1 = bias[col + 1]; }
            float2 v0 = make_float2(acc[mi][ni][0] + b0, acc[mi][ni][1] + b1);
            float2 v1 = make_float2(acc[mi][ni][2] + b0, acc[mi][ni][3] + b1);
            *(float2*)(C + (size_t)row * N + col) = v0;
            *(float2*)(C + (size_t)(row + 8) * N + col) = v1;
        }
    }
}

// ---------------------------------------------------------------------------
// RMSNorm + RoPE on q and k, in place in g_qkv.
// ---------------------------------------------------------------------------
__global__ void __launch_bounds__(512) rmsrope_kernel(
    float* __restrict__ qkv,
    const float* __restrict__ rc, const float* __restrict__ rs,
    const float* __restrict__ qw, const float* __restrict__ kw)
{
    const int bn = blockIdx.x;
    const int n = bn & (NSEQ - 1);
    const int h = threadIdx.x >> 5;
    const int lane = threadIdx.x & 31;

    float* q = qkv + (size_t)bn * C3 + h * HD;
    float* k = q + CDIM;
    const int e1 = lane, e2 = lane + 32;

    const float c1 = rc[n * HD + e1], c2 = rc[n * HD + e2];
    const float s1 = rs[n * HD + e1], s2 = rs[n * HD + e2];

    {
        float a = q[e1], b = q[e2];
        float ss = a * a + b * b;
#pragma unroll
        for (int m = 16; m > 0; m >>= 1) ss += __shfl_xor_sync(0xffffffffu, ss, m);
        float inv = rsqrtf(ss * (1.0f / HD) + 1e-6f);
        a *= inv * qw[e1];
        b *= inv * qw[e2];
        q[e1] = a * c1 - b * s1;
        q[e2] = b * c2 + a * s2;
    }
    {
        float a = k[e1], b = k[e2];
        float ss = a * a + b * b;
#pragma unroll
        for (int m = 16; m > 0; m >>= 1) ss += __shfl_xor_sync(0xffffffffu, ss, m);
        float inv = rsqrtf(ss * (1.0f / HD) + 1e-6f);
        a *= inv * kw[e1];
        b *= inv * kw[e2];
        k[e1] = a * c1 - b * s1;
        k[e2] = b * c2 + a * s2;
    }
}

// ---------------------------------------------------------------------------
// Flash attention fp32 (unchanged this round).
// ---------------------------------------------------------------------------
__global__ void __launch_bounds__(256) attn_kernel(
    const float* __restrict__ qkv, float* __restrict__ out)
{
    extern __shared__ float sm[];
    float* Qs = sm;
    float* Ks = Qs + 64 * 68;
    float* Ps = Ks + 64 * 68;
    float* Vs = Ps + 64 * 68;

    const int qb = blockIdx.x, h = blockIdx.y, b = blockIdx.z;
    const int t = threadIdx.x;
    const int ty = t >> 4, tx = t & 15;

    const size_t base = (size_t)b * NSEQ * C3 + h * HD;

#pragma unroll
    for (int i = 0; i < 4; i++) {
        int idx = t + (i << 8);
        int r = idx >> 4, d4 = (idx & 15) << 2;
        float4 v = *(const float4*)(qkv + base + (size_t)(qb * 64 + r) * C3 + d4);
        Qs[(d4 + 0) * 68 + r] = v.x * 0.125f;
        Qs[(d4 + 1) * 68 + r] = v.y * 0.125f;
        Qs[(d4 + 2) * 68 + r] = v.z * 0.125f;
        Qs[(d4 + 3) * 68 + r] = v.w * 0.125f;
    }

    float o[4][4] = {};
    float mrow[4] = {-1e30f, -1e30f, -1e30f, -1e30f};
    float lrow[4] = {};

    for (int kt = 0; kt < NSEQ / 64; kt++) {
        __syncthreads();
#pragma unroll
        for (int i = 0; i < 4; i++) {
            int idx = t + (i << 8);
            int cc = idx >> 4, d4 = (idx & 15) << 2;
            size_t rowoff = base + (size_t)(kt * 64 + cc) * C3;
            float4 kv = *(const float4*)(qkv + rowoff + CDIM + d4);
            Ks[(d4 + 0) * 68 + cc] = kv.x; Ks[(d4 + 1) * 68 + cc] = kv.y;
            Ks[(d4 + 2) * 68 + cc] = kv.z; Ks[(d4 + 3) * 68 + cc] = kv.w;
            float4 vv = *(const float4*)(qkv + rowoff + 2 * CDIM + d4);
            *(float4*)&Vs[cc * 68 + d4] = vv;
        }
        __syncthreads();

        float s[4][4] = {};
#pragma unroll
        for (int d = 0; d < 64; d++) {
            float4 a = *(float4*)&Qs[d * 68 + (ty << 2)];
            float4 bb = *(float4*)&Ks[d * 68 + (tx << 2)];
            float ar[4] = {a.x, a.y, a.z, a.w};
            float br[4] = {bb.x, bb.y, bb.z, bb.w};
#pragma unroll
            for (int i = 0; i < 4; i++)
#pragma unroll
                for (int j = 0; j < 4; j++)
                    s[i][j] += ar[i] * br[j];
        }

#pragma unroll
        for (int i = 0; i < 4; i++) {
            float mx = fmaxf(fmaxf(s[i][0], s[i][1]), fmaxf(s[i][2], s[i][3]));
#pragma unroll
            for (int msk = 8; msk > 0; msk >>= 1)
                mx = fmaxf(mx, __shfl_xor_sync(0xffffffffu, mx, msk));
            float mn = fmaxf(mrow[i], mx);
            float alpha = __expf(mrow[i] - mn);
            mrow[i] = mn;
            float rsum = 0.0f;
#pragma unroll
            for (int j = 0; j < 4; j++) {
                float p = __expf(s[i][j] - mn);
                s[i][j] = p;
                rsum += p;
            }
#pragma unroll
            for (int msk = 8; msk > 0; msk >>= 1)
                rsum += __shfl_xor_sync(0xffffffffu, rsum, msk);
            lrow[i] = lrow[i] * alpha + rsum;
#pragma unroll
            for (int j = 0; j < 4; j++) o[i][j] *= alpha;
#pragma unroll
            for (int j = 0; j < 4; j++)
                Ps[((tx << 2) + j) * 68 + (ty << 2) + i] = s[i][j];
        }
        __syncthreads();

#pragma unroll
        for (int kk = 0; kk < 64; kk++) {
            float4 p = *(float4*)&Ps[kk * 68 + (ty << 2)];
            float4 v = *(float4*)&Vs[kk * 68 + (tx << 2)];
            float pr[4] = {p.x, p.y, p.z, p.w};
            float vr[4] = {v.x, v.y, v.z, v.w};
#pragma unroll
            for (int i = 0; i < 4; i++)
#pragma unroll
                for (int j = 0; j < 4; j++)
                    o[i][j] += pr[i] * vr[j];
        }
    }

    const size_t obase = (size_t)b * NSEQ * CDIM + h * HD;
#pragma unroll
    for (int i = 0; i < 4; i++) {
        int rr = qb * 64 + (ty << 2) + i;
        float invl = 1.0f / lrow[i];
        float4 w;
        w.x = o[i][0] * invl; w.y = o[i][1] * invl;
        w.z = o[i][2] * invl; w.w = o[i][3] * invl;
        *(float4*)(out + obase + (size_t)rr * CDIM + (tx << 2)) = w;
    }
}

// ---------------------------------------------------------------------------
extern "C" void kernel_launch(void* const* d_in, const int* in_sizes, int n_in,
                              void* d_out, int out_size)
{
    const float* x     = (const float*)d_in[0];
    const float* rc    = (const float*)d_in[1];
    const float* rs    = (const float*)d_in[2];
    const float* wqkv  = (const float*)d_in[3];
    const float* wproj = (const float*)d_in[4];
    const float* bproj = (const float*)d_in[5];
    const float* qw    = (const float*)d_in[6];
    const float* kw    = (const float*)d_in[7];
    float* out = (float*)d_out;

    float *qkv = nullptr, *attn = nullptr;
    cudaGetSymbolAddress((void**)&qkv, g_qkv);
    cudaGetSymbolAddress((void**)&attn, g_attn);

    const int M = BATCH * NSEQ; // 8192

    // 1) QKV projection (tf32 tensor cores)
    gemm_tf32_nt<<<dim3(C3 / 128, M / 128), 256>>>(x, wqkv, nullptr, qkv, M, C3, CDIM);

    // 2) RMSNorm + RoPE in place on q,k
    rmsrope_kernel<<<M, 512>>>(qkv, rc, rs, qw, kw);

    // 3) Flash attention (fp32, unchanged)
    cudaFuncSetAttribute(attn_kernel, cudaFuncAttributeMaxDynamicSharedMemorySize, 69632);
    attn_kernel<<<dim3(NSEQ / 64, HNUM, BATCH), 256, 69632>>>(qkv, attn);

    // 4) Output projection + bias (tf32 tensor cores)
    gemm_tf32_nt<<<dim3(CDIM / 128, M / 128), 256>>>(attn, wproj, bproj, out, M, CDIM, CDIM);
}

// round 6
// speedup vs baseline: 3.4317x; 2.2135x over previous
#include <cuda_runtime.h>
#include <math.h>
#include <stdint.h>

#define BATCH 4
#define NSEQ 2048
#define CDIM 1024
#define HNUM 16
#define HD 64
#define C3 3072

// Scratch (device globals: allocation-free contract)
__device__ float g_qkv[(size_t)BATCH * NSEQ * C3];    // [B,N,3C]
__device__ float g_attn[(size_t)BATCH * NSEQ * CDIM]; // [B,N,C]

__device__ __forceinline__ uint32_t f2tf32(float x) {
    uint32_t r;
    asm("cvt.rna.tf32.f32 %0, %1;" : "=r"(r) : "f"(x));
    return r;
}

__device__ __forceinline__ void mma_tf32(float* d, const uint32_t* a, const uint32_t* b) {
    asm volatile(
        "mma.sync.aligned.m16n8k8.row.col.f32.tf32.tf32.f32 "
        "{%0,%1,%2,%3}, {%4,%5,%6,%7}, {%8,%9}, {%0,%1,%2,%3};"
        : "+f"(d[0]), "+f"(d[1]), "+f"(d[2]), "+f"(d[3])
        : "r"(a[0]), "r"(a[1]), "r"(a[2]), "r"(a[3]), "r"(b[0]), "r"(b[1]));
}

// ---------------------------------------------------------------------------
// TF32 NT GEMM: C[m,n] = sum_k A[m,k]*W[n,k] (+bias)
// Block tile 128x128x32, 256 threads (8 warps, 2x4), warp tile 64x32.
// ---------------------------------------------------------------------------
__global__ void __launch_bounds__(256) gemm_tf32_nt(
    const float* __restrict__ A, const float* __restrict__ W,
    const float* __restrict__ bias, float* __restrict__ C,
    int M, int N, int K)
{
    __shared__ float As[128][36];
    __shared__ float Bs[128][36];

    const int t = threadIdx.x;
    const int wid = t >> 5, lane = t & 31;
    const int wm = wid & 1, wn = wid >> 1;
    const int r = lane >> 2, c = lane & 3;
    const int m0 = blockIdx.y << 7, n0 = blockIdx.x << 7;

    float acc[4][4][4] = {};

    for (int k0 = 0; k0 < K; k0 += 32) {
        __syncthreads();
#pragma unroll
        for (int i = 0; i < 4; i++) {
            int idx = t + (i << 8);
            int row = idx >> 3;
            int c4  = (idx & 7) << 2;
            float4 va = *(const float4*)(A + (size_t)(m0 + row) * K + k0 + c4);
            As[row][c4 + 0] = __uint_as_float(f2tf32(va.x));
            As[row][c4 + 1] = __uint_as_float(f2tf32(va.y));
            As[row][c4 + 2] = __uint_as_float(f2tf32(va.z));
            As[row][c4 + 3] = __uint_as_float(f2tf32(va.w));
            float4 vb = *(const float4*)(W + (size_t)(n0 + row) * K + k0 + c4);
            Bs[row][c4 + 0] = __uint_as_float(f2tf32(vb.x));
            Bs[row][c4 + 1] = __uint_as_float(f2tf32(vb.y));
            Bs[row][c4 + 2] = __uint_as_float(f2tf32(vb.z));
            Bs[row][c4 + 3] = __uint_as_float(f2tf32(vb.w));
        }
        __syncthreads();

#pragma unroll
        for (int kk = 0; kk < 32; kk += 8) {
            uint32_t af[4][4], bf[4][2];
#pragma unroll
            for (int mi = 0; mi < 4; mi++) {
                int mr = (wm << 6) + (mi << 4);
                af[mi][0] = __float_as_uint(As[mr + r    ][kk + c    ]);
                af[mi][1] = __float_as_uint(As[mr + r + 8][kk + c    ]);
                af[mi][2] = __float_as_uint(As[mr + r    ][kk + c + 4]);
                af[mi][3] = __float_as_uint(As[mr + r + 8][kk + c + 4]);
            }
#pragma unroll
            for (int ni = 0; ni < 4; ni++) {
                int nr = (wn << 5) + (ni << 3);
                bf[ni][0] = __float_as_uint(Bs[nr + r][kk + c    ]);
                bf[ni][1] = __float_as_uint(Bs[nr + r][kk + c + 4]);
            }
#pragma unroll
            for (int mi = 0; mi < 4; mi++)
#pragma unroll
                for (int ni = 0; ni < 4; ni++)
                    mma_tf32(acc[mi][ni], af[mi], bf[ni]);
        }
    }

#pragma unroll
    for (int mi = 0; mi < 4; mi++) {
#pragma unroll
        for (int ni = 0; ni < 4; ni++) {
            int row = m0 + (wm << 6) + (mi << 4) + r;
            int col = n0 + (wn << 5) + (ni << 3) + (c << 1);
            float b0 = 0.0f, b1 = 0.0f;
            if (bias) { b0 = bias[col]; b1 = bias[col + 1]; }
            float2 v0 = make_float2(acc[mi][ni][0] + b0, acc[mi][ni][1] + b1);
            float2 v1 = make_float2(acc[mi][ni][2] + b0, acc[mi][ni][3] + b1);
            *(float2*)(C + (size_t)row * N + col) = v0;
            *(float2*)(C + (size_t)(row + 8) * N + col) = v1;
        }
    }
}

// ---------------------------------------------------------------------------
// RMSNorm + RoPE on q and k, in place in g_qkv.
// ---------------------------------------------------------------------------
__global__ void __launch_bounds__(512) rmsrope_kernel(
    float* __restrict__ qkv,
    const float* __restrict__ rc, const float* __restrict__ rs,
    const float* __restrict__ qw, const float* __restrict__ kw)
{
    const int bn = blockIdx.x;
    const int n = bn & (NSEQ - 1);
    const int h = threadIdx.x >> 5;
    const int lane = threadIdx.x & 31;

    float* q = qkv + (size_t)bn * C3 + h * HD;
    float* k = q + CDIM;
    const int e1 = lane, e2 = lane + 32;

    const float c1 = rc[n * HD + e1], c2 = rc[n * HD + e2];
    const float s1 = rs[n * HD + e1], s2 = rs[n * HD + e2];

    {
        float a = q[e1], b = q[e2];
        float ss = a * a + b * b;
#pragma unroll
        for (int m = 16; m > 0; m >>= 1) ss += __shfl_xor_sync(0xffffffffu, ss, m);
        float inv = rsqrtf(ss * (1.0f / HD) + 1e-6f);
        a *= inv * qw[e1];
        b *= inv * qw[e2];
        q[e1] = a * c1 - b * s1;
        q[e2] = b * c2 + a * s2;
    }
    {
        float a = k[e1], b = k[e2];
        float ss = a * a + b * b;
#pragma unroll
        for (int m = 16; m > 0; m >>= 1) ss += __shfl_xor_sync(0xffffffffu, ss, m);
        float inv = rsqrtf(ss * (1.0f / HD) + 1e-6f);
        a *= inv * kw[e1];
        b *= inv * kw[e2];
        k[e1] = a * c1 - b * s1;
        k[e2] = b * c2 + a * s2;
    }
}

// ---------------------------------------------------------------------------
// Tensor-core flash attention (tf32 mma).
// Block: 256 thr / 8 warps; qtile=128 (warp w owns rows w*16..w*16+15),
// ktile=64. Q held as persistent A-fragments in registers. Online softmax
// state per lane: rows r and r+8 of its slab (accumulator-native layout).
// smem: Ks[64][68], Vs[64][72] natural, Ps[128][68] per-warp P staging
// (intra-warp only -> syncwarp). Total 70656 B dynamic.
// ---------------------------------------------------------------------------
#define KS_STRIDE 68
#define VS_STRIDE 72
#define PS_STRIDE 68

__global__ void __launch_bounds__(256) attn_mma_kernel(
    const float* __restrict__ qkv, float* __restrict__ out)
{
    extern __shared__ float sm[];
    float* Ks = sm;                       // [64][68]
    float* Vs = Ks + 64 * KS_STRIDE;      // [64][72]
    float* Ps = Vs + 64 * VS_STRIDE;      // [128][68]

    const int qb = blockIdx.x, h = blockIdx.y, b = blockIdx.z;
    const int t = threadIdx.x;
    const int wid = t >> 5, lane = t & 31;
    const int r = lane >> 2, c = lane & 3;
    const int mr = wid << 4;              // warp's row slab base

    const size_t base = (size_t)b * NSEQ * C3 + h * HD;

    // ---- Stage Q tile (128x64, pre-scaled) into Ps, then grab fragments ----
#pragma unroll
    for (int i = 0; i < 8; i++) {
        int idx = t + (i << 8);           // 0..2047
        int row = idx >> 4;               // 0..127
        int d4  = (idx & 15) << 2;
        float4 v = *(const float4*)(qkv + base + (size_t)(qb * 128 + row) * C3 + d4);
        float4 w = make_float4(v.x * 0.125f, v.y * 0.125f, v.z * 0.125f, v.w * 0.125f);
        *(float4*)&Ps[row * PS_STRIDE + d4] = w;
    }
    __syncthreads();

    uint32_t qa[8][4];
#pragma unroll
    for (int kk = 0; kk < 8; kk++) {
        int k8 = kk << 3;
        qa[kk][0] = f2tf32(Ps[(mr + r    ) * PS_STRIDE + k8 + c    ]);
        qa[kk][1] = f2tf32(Ps[(mr + r + 8) * PS_STRIDE + k8 + c    ]);
        qa[kk][2] = f2tf32(Ps[(mr + r    ) * PS_STRIDE + k8 + c + 4]);
        qa[kk][3] = f2tf32(Ps[(mr + r + 8) * PS_STRIDE + k8 + c + 4]);
    }

    float oacc[8][4] = {};
    float m0 = -1e30f, m1 = -1e30f;
    float l0 = 0.0f,   l1 = 0.0f;

    for (int kt = 0; kt < NSEQ / 64; kt++) {
        __syncthreads();
        // ---- Load K and V tiles (tf32-converted) ----
#pragma unroll
        for (int i = 0; i < 4; i++) {
            int idx = t + (i << 8);       // 0..1023
            int row = idx >> 4;           // 0..63
            int d4  = (idx & 15) << 2;
            size_t rowoff = base + (size_t)(kt * 64 + row) * C3;
            float4 kv = *(const float4*)(qkv + rowoff + CDIM + d4);
            float4 kc;
            kc.x = __uint_as_float(f2tf32(kv.x)); kc.y = __uint_as_float(f2tf32(kv.y));
            kc.z = __uint_as_float(f2tf32(kv.z)); kc.w = __uint_as_float(f2tf32(kv.w));
            *(float4*)&Ks[row * KS_STRIDE + d4] = kc;
            float4 vv = *(const float4*)(qkv + rowoff + 2 * CDIM + d4);
            float4 vc;
            vc.x = __uint_as_float(f2tf32(vv.x)); vc.y = __uint_as_float(f2tf32(vv.y));
            vc.z = __uint_as_float(f2tf32(vv.z)); vc.w = __uint_as_float(f2tf32(vv.w));
            *(float4*)&Vs[row * VS_STRIDE + d4] = vc;
        }
        __syncthreads();

        // ---- S = Q K^T : warp computes 16x64 ----
        float sacc[8][4] = {};
#pragma unroll
        for (int kk = 0; kk < 8; kk++) {
            int k8 = kk << 3;
            uint32_t bf[8][2];
#pragma unroll
            for (int ni = 0; ni < 8; ni++) {
                bf[ni][0] = __float_as_uint(Ks[(ni * 8 + r) * KS_STRIDE + k8 + c    ]);
                bf[ni][1] = __float_as_uint(Ks[(ni * 8 + r) * KS_STRIDE + k8 + c + 4]);
            }
#pragma unroll
            for (int ni = 0; ni < 8; ni++)
                mma_tf32(sacc[ni], qa[kk], bf[ni]);
        }

        // ---- Online softmax: rows r (regs 0,1) and r+8 (regs 2,3) ----
        float mx0 = -1e30f, mx1 = -1e30f;
#pragma unroll
        for (int ni = 0; ni < 8; ni++) {
            mx0 = fmaxf(mx0, fmaxf(sacc[ni][0], sacc[ni][1]));
            mx1 = fmaxf(mx1, fmaxf(sacc[ni][2], sacc[ni][3]));
        }
        mx0 = fmaxf(mx0, __shfl_xor_sync(0xffffffffu, mx0, 1));
        mx0 = fmaxf(mx0, __shfl_xor_sync(0xffffffffu, mx0, 2));
        mx1 = fmaxf(mx1, __shfl_xor_sync(0xffffffffu, mx1, 1));
        mx1 = fmaxf(mx1, __shfl_xor_sync(0xffffffffu, mx1, 2));

        float mn0 = fmaxf(m0, mx0), mn1 = fmaxf(m1, mx1);
        float al0 = __expf(m0 - mn0), al1 = __expf(m1 - mn1);
        m0 = mn0; m1 = mn1;

        float sum0 = 0.0f, sum1 = 0.0f;
#pragma unroll
        for (int ni = 0; ni < 8; ni++) {
            float p0 = __expf(sacc[ni][0] - mn0);
            float p1 = __expf(sacc[ni][1] - mn0);
            float p2 = __expf(sacc[ni][2] - mn1);
            float p3 = __expf(sacc[ni][3] - mn1);
            sum0 += p0 + p1; sum1 += p2 + p3;
            int col = (ni << 3) + (c << 1);
            float2 w0 = make_float2(__uint_as_float(f2tf32(p0)), __uint_as_float(f2tf32(p1)));
            float2 w1 = make_float2(__uint_as_float(f2tf32(p2)), __uint_as_float(f2tf32(p3)));
            *(float2*)&Ps[(mr + r    ) * PS_STRIDE + col] = w0;
            *(float2*)&Ps[(mr + r + 8) * PS_STRIDE + col] = w1;
        }
        sum0 += __shfl_xor_sync(0xffffffffu, sum0, 1);
        sum0 += __shfl_xor_sync(0xffffffffu, sum0, 2);
        sum1 += __shfl_xor_sync(0xffffffffu, sum1, 1);
        sum1 += __shfl_xor_sync(0xffffffffu, sum1, 2);
        l0 = l0 * al0 + sum0;
        l1 = l1 * al1 + sum1;

#pragma unroll
        for (int ni = 0; ni < 8; ni++) {
            oacc[ni][0] *= al0; oacc[ni][1] *= al0;
            oacc[ni][2] *= al1; oacc[ni][3] *= al1;
        }
        __syncwarp();   // P slab is intra-warp: written/read by same warp

        // ---- O += P V : A from Ps (own slab), B from Vs ----
#pragma unroll
        for (int kk = 0; kk < 8; kk++) {
            int k8 = kk << 3;
            uint32_t pa[4];
            pa[0] = __float_as_uint(Ps[(mr + r    ) * PS_STRIDE + k8 + c    ]);
            pa[1] = __float_as_uint(Ps[(mr + r + 8) * PS_STRIDE + k8 + c    ]);
            pa[2] = __float_as_uint(Ps[(mr + r    ) * PS_STRIDE + k8 + c + 4]);
            pa[3] = __float_as_uint(Ps[(mr + r + 8) * PS_STRIDE + k8 + c + 4]);
            uint32_t bf[8][2];
#pragma unroll
            for (int ni = 0; ni < 8; ni++) {
                bf[ni][0] = __float_as_uint(Vs[(k8 + c    ) * VS_STRIDE + (ni << 3) + r]);
                bf[ni][1] = __float_as_uint(Vs[(k8 + c + 4) * VS_STRIDE + (ni << 3) + r]);
            }
#pragma unroll
            for (int ni = 0; ni < 8; ni++)
                mma_tf32(oacc[ni], pa, bf[ni]);
        }
        __syncwarp();   // done with Ps before next iteration's reuse
    }

    // ---- Epilogue: normalize, write [B,N,C] ----
    const size_t obase = (size_t)b * NSEQ * CDIM + h * HD;
    const float invl0 = 1.0f / l0, invl1 = 1.0f / l1;
    const int row0 = qb * 128 + mr + r;
#pragma unroll
    for (int ni = 0; ni < 8; ni++) {
        int col = (ni << 3) + (c << 1);
        float2 w0 = make_float2(oacc[ni][0] * invl0, oacc[ni][1] * invl0);
        float2 w1 = make_float2(oacc[ni][2] * invl1, oacc[ni][3] * invl1);
        *(float2*)(out + obase + (size_t)row0 * CDIM + col) = w0;
        *(float2*)(out + obase + (size_t)(row0 + 8) * CDIM + col) = w1;
    }
}

// ---------------------------------------------------------------------------
extern "C" void kernel_launch(void* const* d_in, const int* in_sizes, int n_in,
                              void* d_out, int out_size)
{
    const float* x     = (const float*)d_in[0];
    const float* rc    = (const float*)d_in[1];
    const float* rs    = (const float*)d_in[2];
    const float* wqkv  = (const float*)d_in[3];
    const float* wproj = (const float*)d_in[4];
    const float* bproj = (const float*)d_in[5];
    const float* qw    = (const float*)d_in[6];
    const float* kw    = (const float*)d_in[7];
    float* out = (float*)d_out;

    float *qkv = nullptr, *attn = nullptr;
    cudaGetSymbolAddress((void**)&qkv, g_qkv);
    cudaGetSymbolAddress((void**)&attn, g_attn);

    const int M = BATCH * NSEQ; // 8192
    const int ATTN_SMEM = (64 * KS_STRIDE + 64 * VS_STRIDE + 128 * PS_STRIDE) * 4; // 70656

    // 1) QKV projection (tf32 tensor cores)
    gemm_tf32_nt<<<dim3(C3 / 128, M / 128), 256>>>(x, wqkv, nullptr, qkv, M, C3, CDIM);

    // 2) RMSNorm + RoPE in place on q,k
    rmsrope_kernel<<<M, 512>>>(qkv, rc, rs, qw, kw);

    // 3) Flash attention (tf32 tensor cores)
    cudaFuncSetAttribute(attn_mma_kernel, cudaFuncAttributeMaxDynamicSharedMemorySize, ATTN_SMEM);
    attn_mma_kernel<<<dim3(NSEQ / 128, HNUM, BATCH), 256, ATTN_SMEM>>>(qkv, attn);

    // 4) Output projection + bias (tf32 tensor cores)
    gemm_tf32_nt<<<dim3(CDIM / 128, M / 128), 256>>>(attn, wproj, bproj, out, M, CDIM, CDIM);
}

// round 7
// speedup vs baseline: 3.9628x; 1.1547x over previous
#include <cuda_runtime.h>
#include <math.h>
#include <stdint.h>

#define BATCH 4
#define NSEQ 2048
#define CDIM 1024
#define HNUM 16
#define HD 64
#define C3 3072

// Scratch (device globals: allocation-free contract)
__device__ float g_qkv[(size_t)BATCH * NSEQ * C3];     // [B,N,3C]
__device__ float g_attn[(size_t)BATCH * NSEQ * CDIM];  // [B,N,C]
__device__ float g_xr[(size_t)BATCH * NSEQ * CDIM];    // tf32-rounded x
__device__ float g_wqkvr[(size_t)C3 * CDIM];           // tf32-rounded w_qkv
__device__ float g_wprojr[(size_t)CDIM * CDIM];        // tf32-rounded w_proj

__device__ __forceinline__ uint32_t f2tf32(float x) {
    uint32_t r;
    asm("cvt.rna.tf32.f32 %0, %1;" : "=r"(r) : "f"(x));
    return r;
}
__device__ __forceinline__ float rnd(float x) { return __uint_as_float(f2tf32(x)); }

__device__ __forceinline__ void mma_tf32(float* d, const uint32_t* a, const uint32_t* b) {
    asm volatile(
        "mma.sync.aligned.m16n8k8.row.col.f32.tf32.tf32.f32 "
        "{%0,%1,%2,%3}, {%4,%5,%6,%7}, {%8,%9}, {%0,%1,%2,%3};"
        : "+f"(d[0]), "+f"(d[1]), "+f"(d[2]), "+f"(d[3])
        : "r"(a[0]), "r"(a[1]), "r"(a[2]), "r"(a[3]), "r"(b[0]), "r"(b[1]));
}

__device__ __forceinline__ void cp16(uint32_t dst, const void* src) {
    asm volatile("cp.async.ca.shared.global [%0], [%1], 16;" :: "r"(dst), "l"(src));
}
__device__ __forceinline__ void cp_commit() { asm volatile("cp.async.commit_group;"); }
template <int N> __device__ __forceinline__ void cp_wait() {
    asm volatile("cp.async.wait_group %0;" :: "n"(N));
}
__device__ __forceinline__ uint32_t smem_u32(const void* p) {
    return (uint32_t)__cvta_generic_to_shared(p);
}

// ---------------------------------------------------------------------------
// Round fp32 -> tf32-valid fp32 (elementwise, float4)
// ---------------------------------------------------------------------------
__global__ void __launch_bounds__(256) round_tf32_kernel(
    const float4* __restrict__ in, float4* __restrict__ out, int n4)
{
    int i = blockIdx.x * blockDim.x + threadIdx.x;
    if (i < n4) {
        float4 v = in[i];
        v.x = rnd(v.x); v.y = rnd(v.y); v.z = rnd(v.z); v.w = rnd(v.w);
        out[i] = v;
    }
}

// ---------------------------------------------------------------------------
// TF32 NT GEMM, cp.async 2-stage pipeline. Inputs must be tf32-valid fp32.
// C[m,n] = sum_k A[m,k]*W[n,k] (+bias); round_out: tf32-round the output.
// Block tile 128x128x32, 256 thr (8 warps 2x4), warp tile 64x32.
// Dynamic smem: 2*2*128*36*4 = 73728 B.
// ---------------------------------------------------------------------------
__global__ void __launch_bounds__(256) gemm_tf32_cp(
    const float* __restrict__ A, const float* __restrict__ W,
    const float* __restrict__ bias, float* __restrict__ C,
    int M, int N, int K, int round_out)
{
    extern __shared__ float sm[];
    float* As = sm;                 // [2][128][36]
    float* Bs = sm + 2 * 128 * 36;  // [2][128][36]

    const int t = threadIdx.x;
    const int wid = t >> 5, lane = t & 31;
    const int wm = wid & 1, wn = wid >> 1;
    const int r = lane >> 2, c = lane & 3;
    const int m0 = blockIdx.y << 7, n0 = blockIdx.x << 7;

    auto issue = [&](int k0, int s) {
        float* as = As + s * 128 * 36;
        float* bs = Bs + s * 128 * 36;
#pragma unroll
        for (int i = 0; i < 4; i++) {
            int idx = t + (i << 8);
            int row = idx >> 3;
            int c4  = (idx & 7) << 2;
            cp16(smem_u32(&as[row * 36 + c4]), A + (size_t)(m0 + row) * K + k0 + c4);
            cp16(smem_u32(&bs[row * 36 + c4]), W + (size_t)(n0 + row) * K + k0 + c4);
        }
        cp_commit();
    };

    float acc[4][4][4] = {};
    issue(0, 0);
    int s = 0;

    for (int k0 = 0; k0 < K; k0 += 32) {
        if (k0 + 32 < K) { issue(k0 + 32, s ^ 1); cp_wait<1>(); }
        else             { cp_wait<0>(); }
        __syncthreads();

        const float* as = As + s * 128 * 36;
        const float* bs = Bs + s * 128 * 36;
#pragma unroll
        for (int kk = 0; kk < 32; kk += 8) {
            uint32_t af[4][4], bf[4][2];
#pragma unroll
            for (int mi = 0; mi < 4; mi++) {
                int mr = (wm << 6) + (mi << 4);
                af[mi][0] = __float_as_uint(as[(mr + r    ) * 36 + kk + c    ]);
                af[mi][1] = __float_as_uint(as[(mr + r + 8) * 36 + kk + c    ]);
                af[mi][2] = __float_as_uint(as[(mr + r    ) * 36 + kk + c + 4]);
                af[mi][3] = __float_as_uint(as[(mr + r + 8) * 36 + kk + c + 4]);
            }
#pragma unroll
            for (int ni = 0; ni < 4; ni++) {
                int nr = (wn << 5) + (ni << 3);
                bf[ni][0] = __float_as_uint(bs[(nr + r) * 36 + kk + c    ]);
                bf[ni][1] = __float_as_uint(bs[(nr + r) * 36 + kk + c + 4]);
            }
#pragma unroll
            for (int mi = 0; mi < 4; mi++)
#pragma unroll
                for (int ni = 0; ni < 4; ni++)
                    mma_tf32(acc[mi][ni], af[mi], bf[ni]);
        }
        __syncthreads();
        s ^= 1;
    }

#pragma unroll
    for (int mi = 0; mi < 4; mi++) {
#pragma unroll
        for (int ni = 0; ni < 4; ni++) {
            int row = m0 + (wm << 6) + (mi << 4) + r;
            int col = n0 + (wn << 5) + (ni << 3) + (c << 1);
            float o0 = acc[mi][ni][0], o1 = acc[mi][ni][1];
            float o2 = acc[mi][ni][2], o3 = acc[mi][ni][3];
            if (round_out) { o0 = rnd(o0); o1 = rnd(o1); o2 = rnd(o2); o3 = rnd(o3); }
            if (bias) {
                float b0 = bias[col], b1 = bias[col + 1];
                o0 += b0; o1 += b1; o2 += b0; o3 += b1;
            }
            *(float2*)(C + (size_t)row * N + col) = make_float2(o0, o1);
            *(float2*)(C + (size_t)(row + 8) * N + col) = make_float2(o2, o3);
        }
    }
}

// ---------------------------------------------------------------------------
// RMSNorm + RoPE on q and k, in place. Writes tf32-rounded values; q is
// additionally pre-scaled by hd^-0.5 = 0.125 (exact power of 2).
// ---------------------------------------------------------------------------
__global__ void __launch_bounds__(512) rmsrope_kernel(
    float* __restrict__ qkv,
    const float* __restrict__ rc, const float* __restrict__ rs,
    const float* __restrict__ qw, const float* __restrict__ kw)
{
    const int bn = blockIdx.x;
    const int n = bn & (NSEQ - 1);
    const int h = threadIdx.x >> 5;
    const int lane = threadIdx.x & 31;

    float* q = qkv + (size_t)bn * C3 + h * HD;
    float* k = q + CDIM;
    const int e1 = lane, e2 = lane + 32;

    const float c1 = rc[n * HD + e1], c2 = rc[n * HD + e2];
    const float s1 = rs[n * HD + e1], s2 = rs[n * HD + e2];

    {
        float a = q[e1], b = q[e2];
        float ss = a * a + b * b;
#pragma unroll
        for (int m = 16; m > 0; m >>= 1) ss += __shfl_xor_sync(0xffffffffu, ss, m);
        float inv = rsqrtf(ss * (1.0f / HD) + 1e-6f);
        a *= inv * qw[e1];
        b *= inv * qw[e2];
        q[e1] = rnd((a * c1 - b * s1) * 0.125f);
        q[e2] = rnd((b * c2 + a * s2) * 0.125f);
    }
    {
        float a = k[e1], b = k[e2];
        float ss = a * a + b * b;
#pragma unroll
        for (int m = 16; m > 0; m >>= 1) ss += __shfl_xor_sync(0xffffffffu, ss, m);
        float inv = rsqrtf(ss * (1.0f / HD) + 1e-6f);
        a *= inv * kw[e1];
        b *= inv * kw[e2];
        k[e1] = rnd(a * c1 - b * s1);
        k[e2] = rnd(b * c2 + a * s2);
    }
}

// ---------------------------------------------------------------------------
// Tensor-core flash attention, cp.async 2-stage K/V pipeline.
// qkv q/k/v values must already be tf32-valid (q pre-scaled).
// Block 256 thr / 8 warps; qtile=128, ktile=64. Output tf32-rounded.
// smem: Ks[2][64][68], Vs[2][64][72], Ps[128][68] = 106496 B dynamic.
// ---------------------------------------------------------------------------
#define KS_STRIDE 68
#define VS_STRIDE 72
#define PS_STRIDE 68

__global__ void __launch_bounds__(256) attn_mma_kernel(
    const float* __restrict__ qkv, float* __restrict__ out)
{
    extern __shared__ float sm[];
    float* Ks = sm;                          // [2][64][68]
    float* Vs = sm + 2 * 64 * KS_STRIDE;     // [2][64][72]
    float* Ps = Vs + 2 * 64 * VS_STRIDE;     // [128][68]

    const int qb = blockIdx.x, h = blockIdx.y, b = blockIdx.z;
    const int t = threadIdx.x;
    const int wid = t >> 5, lane = t & 31;
    const int r = lane >> 2, c = lane & 3;
    const int mr = wid << 4;

    const size_t base = (size_t)b * NSEQ * C3 + h * HD;

    // ---- Prologue: async-load Q into Ps, then K/V tile 0 into stage 0 ----
#pragma unroll
    for (int i = 0; i < 8; i++) {
        int idx = t + (i << 8);
        int row = idx >> 4;
        int d4  = (idx & 15) << 2;
        cp16(smem_u32(&Ps[row * PS_STRIDE + d4]),
             qkv + base + (size_t)(qb * 128 + row) * C3 + d4);
    }
    cp_commit();

    auto issue_kv = [&](int kt, int s) {
        float* ks = Ks + s * 64 * KS_STRIDE;
        float* vs = Vs + s * 64 * VS_STRIDE;
#pragma unroll
        for (int i = 0; i < 4; i++) {
            int idx = t + (i << 8);
            int row = idx >> 4;
            int d4  = (idx & 15) << 2;
            const float* src = qkv + base + (size_t)(kt * 64 + row) * C3 + d4;
            cp16(smem_u32(&ks[row * KS_STRIDE + d4]), src + CDIM);
            cp16(smem_u32(&vs[row * VS_STRIDE + d4]), src + 2 * CDIM);
        }
        cp_commit();
    };
    issue_kv(0, 0);

    cp_wait<1>();          // Q complete (tile 0 may still be in flight)
    __syncthreads();

    uint32_t qa[8][4];
#pragma unroll
    for (int kk = 0; kk < 8; kk++) {
        int k8 = kk << 3;
        qa[kk][0] = __float_as_uint(Ps[(mr + r    ) * PS_STRIDE + k8 + c    ]);
        qa[kk][1] = __float_as_uint(Ps[(mr + r + 8) * PS_STRIDE + k8 + c    ]);
        qa[kk][2] = __float_as_uint(Ps[(mr + r    ) * PS_STRIDE + k8 + c + 4]);
        qa[kk][3] = __float_as_uint(Ps[(mr + r + 8) * PS_STRIDE + k8 + c + 4]);
    }

    float oacc[8][4] = {};
    float m0 = -1e30f, m1 = -1e30f;
    float l0 = 0.0f,   l1 = 0.0f;
    int s = 0;

    for (int kt = 0; kt < NSEQ / 64; kt++) {
        if (kt + 1 < NSEQ / 64) { issue_kv(kt + 1, s ^ 1); cp_wait<1>(); }
        else                    { cp_wait<0>(); }
        __syncthreads();

        const float* ks = Ks + s * 64 * KS_STRIDE;
        const float* vs = Vs + s * 64 * VS_STRIDE;

        // ---- S = Q K^T ----
        float sacc[8][4] = {};
#pragma unroll
        for (int kk = 0; kk < 8; kk++) {
            int k8 = kk << 3;
            uint32_t bf[8][2];
#pragma unroll
            for (int ni = 0; ni < 8; ni++) {
                bf[ni][0] = __float_as_uint(ks[(ni * 8 + r) * KS_STRIDE + k8 + c    ]);
                bf[ni][1] = __float_as_uint(ks[(ni * 8 + r) * KS_STRIDE + k8 + c + 4]);
            }
#pragma unroll
            for (int ni = 0; ni < 8; ni++)
                mma_tf32(sacc[ni], qa[kk], bf[ni]);
        }

        // ---- Online softmax ----
        float mx0 = -1e30f, mx1 = -1e30f;
#pragma unroll
        for (int ni = 0; ni < 8; ni++) {
            mx0 = fmaxf(mx0, fmaxf(sacc[ni][0], sacc[ni][1]));
            mx1 = fmaxf(mx1, fmaxf(sacc[ni][2], sacc[ni][3]));
        }
        mx0 = fmaxf(mx0, __shfl_xor_sync(0xffffffffu, mx0, 1));
        mx0 = fmaxf(mx0, __shfl_xor_sync(0xffffffffu, mx0, 2));
        mx1 = fmaxf(mx1, __shfl_xor_sync(0xffffffffu, mx1, 1));
        mx1 = fmaxf(mx1, __shfl_xor_sync(0xffffffffu, mx1, 2));

        float mn0 = fmaxf(m0, mx0), mn1 = fmaxf(m1, mx1);
        float al0 = __expf(m0 - mn0), al1 = __expf(m1 - mn1);
        m0 = mn0; m1 = mn1;

        float sum0 = 0.0f, sum1 = 0.0f;
#pragma unroll
        for (int ni = 0; ni < 8; ni++) {
            float p0 = __expf(sacc[ni][0] - mn0);
            float p1 = __expf(sacc[ni][1] - mn0);
            float p2 = __expf(sacc[ni][2] - mn1);
            float p3 = __expf(sacc[ni][3] - mn1);
            sum0 += p0 + p1; sum1 += p2 + p3;
            int col = (ni << 3) + (c << 1);
            float2 w0 = make_float2(rnd(p0), rnd(p1));
            float2 w1 = make_float2(rnd(p2), rnd(p3));
            *(float2*)&Ps[(mr + r    ) * PS_STRIDE + col] = w0;
            *(float2*)&Ps[(mr + r + 8) * PS_STRIDE + col] = w1;
        }
        sum0 += __shfl_xor_sync(0xffffffffu, sum0, 1);
        sum0 += __shfl_xor_sync(0xffffffffu, sum0, 2);
        sum1 += __shfl_xor_sync(0xffffffffu, sum1, 1);
        sum1 += __shfl_xor_sync(0xffffffffu, sum1, 2);
        l0 = l0 * al0 + sum0;
        l1 = l1 * al1 + sum1;

#pragma unroll
        for (int ni = 0; ni < 8; ni++) {
            oacc[ni][0] *= al0; oacc[ni][1] *= al0;
            oacc[ni][2] *= al1; oacc[ni][3] *= al1;
        }
        __syncwarp();   // P slab is intra-warp

        // ---- O += P V ----
#pragma unroll
        for (int kk = 0; kk < 8; kk++) {
            int k8 = kk << 3;
            uint32_t pa[4];
            pa[0] = __float_as_uint(Ps[(mr + r    ) * PS_STRIDE + k8 + c    ]);
            pa[1] = __float_as_uint(Ps[(mr + r + 8) * PS_STRIDE + k8 + c    ]);
            pa[2] = __float_as_uint(Ps[(mr + r    ) * PS_STRIDE + k8 + c + 4]);
            pa[3] = __float_as_uint(Ps[(mr + r + 8) * PS_STRIDE + k8 + c + 4]);
            uint32_t bf[8][2];
#pragma unroll
            for (int ni = 0; ni < 8; ni++) {
                bf[ni][0] = __float_as_uint(vs[(k8 + c    ) * VS_STRIDE + (ni << 3) + r]);
                bf[ni][1] = __float_as_uint(vs[(k8 + c + 4) * VS_STRIDE + (ni << 3) + r]);
            }
#pragma unroll
            for (int ni = 0; ni < 8; ni++)
                mma_tf32(oacc[ni], pa, bf[ni]);
        }
        __syncthreads();   // all reads of this stage done before it is refilled
        s ^= 1;
    }

    // ---- Epilogue: normalize, tf32-round, write [B,N,C] ----
    const size_t obase = (size_t)b * NSEQ * CDIM + h * HD;
    const float invl0 = 1.0f / l0, invl1 = 1.0f / l1;
    const int row0 = qb * 128 + mr + r;
#pragma unroll
    for (int ni = 0; ni < 8; ni++) {
        int col = (ni << 3) + (c << 1);
        float2 w0 = make_float2(rnd(oacc[ni][0] * invl0), rnd(oacc[ni][1] * invl0));
        float2 w1 = make_float2(rnd(oacc[ni][2] * invl1), rnd(oacc[ni][3] * invl1));
        *(float2*)(out + obase + (size_t)row0 * CDIM + col) = w0;
        *(float2*)(out + obase + (size_t)(row0 + 8) * CDIM + col) = w1;
    }
}

// ---------------------------------------------------------------------------
extern "C" void kernel_launch(void* const* d_in, const int* in_sizes, int n_in,
                              void* d_out, int out_size)
{
    const float* x     = (const float*)d_in[0];
    const float* rc    = (const float*)d_in[1];
    const float* rs    = (const float*)d_in[2];
    const float* wqkv  = (const float*)d_in[3];
    const float* wproj = (const float*)d_in[4];
    const float* bproj = (const float*)d_in[5];
    const float* qw    = (const float*)d_in[6];
    const float* kw    = (const float*)d_in[7];
    float* out = (float*)d_out;

    float *qkv, *attn, *xr, *wqkvr, *wprojr;
    cudaGetSymbolAddress((void**)&qkv, g_qkv);
    cudaGetSymbolAddress((void**)&attn, g_attn);
    cudaGetSymbolAddress((void**)&xr, g_xr);
    cudaGetSymbolAddress((void**)&wqkvr, g_wqkvr);
    cudaGetSymbolAddress((void**)&wprojr, g_wprojr);

    const int M = BATCH * NSEQ; // 8192
    const int GEMM_SMEM = 2 * 2 * 128 * 36 * 4;                                   // 73728
    const int ATTN_SMEM = (2 * 64 * KS_STRIDE + 2 * 64 * VS_STRIDE + 128 * PS_STRIDE) * 4; // 106496

    static int attrs_set = 0;
    cudaFuncSetAttribute(gemm_tf32_cp, cudaFuncAttributeMaxDynamicSharedMemorySize, GEMM_SMEM);
    cudaFuncSetAttribute(attn_mma_kernel, cudaFuncAttributeMaxDynamicSharedMemorySize, ATTN_SMEM);
    (void)attrs_set;

    // 0) Round inputs to tf32-valid fp32
    {
        int n4x = M * CDIM / 4;          // 2097152
        int n4q = C3 * CDIM / 4;         // 786432
        int n4p = CDIM * CDIM / 4;       // 262144
        round_tf32_kernel<<<(n4x + 255) / 256, 256>>>((const float4*)x, (float4*)xr, n4x);
        round_tf32_kernel<<<(n4q + 255) / 256, 256>>>((const float4*)wqkv, (float4*)wqkvr, n4q);
        round_tf32_kernel<<<(n4p + 255) / 256, 256>>>((const float4*)wproj, (float4*)wprojr, n4p);
    }

    // 1) QKV projection (output tf32-rounded so attention can raw-copy V)
    gemm_tf32_cp<<<dim3(C3 / 128, M / 128), 256, GEMM_SMEM>>>(
        xr, wqkvr, nullptr, qkv, M, C3, CDIM, 1);

    // 2) RMSNorm + RoPE in place (writes tf32-rounded q*0.125, k)
    rmsrope_kernel<<<M, 512>>>(qkv, rc, rs, qw, kw);

    // 3) Flash attention (cp.async pipelined; output tf32-rounded)
    attn_mma_kernel<<<dim3(NSEQ / 128, HNUM, BATCH), 256, ATTN_SMEM>>>(qkv, attn);

    // 4) Output projection + bias
    gemm_tf32_cp<<<dim3(CDIM / 128, M / 128), 256, GEMM_SMEM>>>(
        attn, wprojr, bproj, out, M, CDIM, CDIM, 0);
}

// round 8
// speedup vs baseline: 4.0687x; 1.0267x over previous
#include <cuda_runtime.h>
#include <math.h>
#include <stdint.h>

#define BATCH 4
#define NSEQ 2048
#define CDIM 1024
#define HNUM 16
#define HD 64
#define C3 3072

// Scratch (device globals: allocation-free contract)
__device__ float g_qkv[(size_t)BATCH * NSEQ * C3];     // [B,N,3C]
__device__ float g_attn[(size_t)BATCH * NSEQ * CDIM];  // [B,N,C]
__device__ float g_xr[(size_t)BATCH * NSEQ * CDIM];    // tf32-rounded x
__device__ float g_wqkvr[(size_t)C3 * CDIM];           // tf32-rounded w_qkv
__device__ float g_wprojr[(size_t)CDIM * CDIM];        // tf32-rounded w_proj

__device__ __forceinline__ uint32_t f2tf32(float x) {
    uint32_t r;
    asm("cvt.rna.tf32.f32 %0, %1;" : "=r"(r) : "f"(x));
    return r;
}
__device__ __forceinline__ float rnd(float x) { return __uint_as_float(f2tf32(x)); }

__device__ __forceinline__ void mma_tf32(float* d, const uint32_t* a, const uint32_t* b) {
    asm volatile(
        "mma.sync.aligned.m16n8k8.row.col.f32.tf32.tf32.f32 "
        "{%0,%1,%2,%3}, {%4,%5,%6,%7}, {%8,%9}, {%0,%1,%2,%3};"
        : "+f"(d[0]), "+f"(d[1]), "+f"(d[2]), "+f"(d[3])
        : "r"(a[0]), "r"(a[1]), "r"(a[2]), "r"(a[3]), "r"(b[0]), "r"(b[1]));
}

__device__ __forceinline__ void cp16(uint32_t dst, const void* src) {
    asm volatile("cp.async.ca.shared.global [%0], [%1], 16;" :: "r"(dst), "l"(src));
}
__device__ __forceinline__ void cp_commit() { asm volatile("cp.async.commit_group;"); }
template <int N> __device__ __forceinline__ void cp_wait() {
    asm volatile("cp.async.wait_group %0;" :: "n"(N));
}
__device__ __forceinline__ uint32_t smem_u32(const void* p) {
    return (uint32_t)__cvta_generic_to_shared(p);
}

// ---------------------------------------------------------------------------
// Round fp32 -> tf32-valid fp32 (elementwise, float4)
// ---------------------------------------------------------------------------
__global__ void __launch_bounds__(256) round_tf32_kernel(
    const float4* __restrict__ in, float4* __restrict__ out, int n4)
{
    int i = blockIdx.x * blockDim.x + threadIdx.x;
    if (i < n4) {
        float4 v = in[i];
        v.x = rnd(v.x); v.y = rnd(v.y); v.z = rnd(v.z); v.w = rnd(v.w);
        out[i] = v;
    }
}

// ---------------------------------------------------------------------------
// TF32 NT GEMM, cp.async 2-stage pipeline. Inputs must be tf32-valid fp32.
// C[m,n] = sum_k A[m,k]*W[n,k] (+bias); round_out: tf32-round the output.
// Block tile 128x128x32, 256 thr (8 warps 2x4), warp tile 64x32.
// __launch_bounds__(256,2): cap regs at 128 so 2 CTAs co-reside per SM.
// Dynamic smem: 2*2*128*36*4 = 73728 B (x2 CTAs = 147456 < 228K).
// ---------------------------------------------------------------------------
__global__ void __launch_bounds__(256, 2) gemm_tf32_cp(
    const float* __restrict__ A, const float* __restrict__ W,
    const float* __restrict__ bias, float* __restrict__ C,
    int M, int N, int K, int round_out)
{
    extern __shared__ float sm[];
    float* As = sm;                 // [2][128][36]
    float* Bs = sm + 2 * 128 * 36;  // [2][128][36]

    const int t = threadIdx.x;
    const int wid = t >> 5, lane = t & 31;
    const int wm = wid & 1, wn = wid >> 1;
    const int r = lane >> 2, c = lane & 3;
    const int m0 = blockIdx.y << 7, n0 = blockIdx.x << 7;

    auto issue = [&](int k0, int s) {
        float* as = As + s * 128 * 36;
        float* bs = Bs + s * 128 * 36;
#pragma unroll
        for (int i = 0; i < 4; i++) {
            int idx = t + (i << 8);
            int row = idx >> 3;
            int c4  = (idx & 7) << 2;
            cp16(smem_u32(&as[row * 36 + c4]), A + (size_t)(m0 + row) * K + k0 + c4);
            cp16(smem_u32(&bs[row * 36 + c4]), W + (size_t)(n0 + row) * K + k0 + c4);
        }
        cp_commit();
    };

    float acc[4][4][4] = {};
    issue(0, 0);
    int s = 0;

    for (int k0 = 0; k0 < K; k0 += 32) {
        if (k0 + 32 < K) { issue(k0 + 32, s ^ 1); cp_wait<1>(); }
        else             { cp_wait<0>(); }
        __syncthreads();

        const float* as = As + s * 128 * 36;
        const float* bs = Bs + s * 128 * 36;
#pragma unroll
        for (int kk = 0; kk < 32; kk += 8) {
            uint32_t af[4][4], bf[4][2];
#pragma unroll
            for (int mi = 0; mi < 4; mi++) {
                int mr = (wm << 6) + (mi << 4);
                af[mi][0] = __float_as_uint(as[(mr + r    ) * 36 + kk + c    ]);
                af[mi][1] = __float_as_uint(as[(mr + r + 8) * 36 + kk + c    ]);
                af[mi][2] = __float_as_uint(as[(mr + r    ) * 36 + kk + c + 4]);
                af[mi][3] = __float_as_uint(as[(mr + r + 8) * 36 + kk + c + 4]);
            }
#pragma unroll
            for (int ni = 0; ni < 4; ni++) {
                int nr = (wn << 5) + (ni << 3);
                bf[ni][0] = __float_as_uint(bs[(nr + r) * 36 + kk + c    ]);
                bf[ni][1] = __float_as_uint(bs[(nr + r) * 36 + kk + c + 4]);
            }
#pragma unroll
            for (int mi = 0; mi < 4; mi++)
#pragma unroll
                for (int ni = 0; ni < 4; ni++)
                    mma_tf32(acc[mi][ni], af[mi], bf[ni]);
        }
        __syncthreads();
        s ^= 1;
    }

#pragma unroll
    for (int mi = 0; mi < 4; mi++) {
#pragma unroll
        for (int ni = 0; ni < 4; ni++) {
            int row = m0 + (wm << 6) + (mi << 4) + r;
            int col = n0 + (wn << 5) + (ni << 3) + (c << 1);
            float o0 = acc[mi][ni][0], o1 = acc[mi][ni][1];
            float o2 = acc[mi][ni][2], o3 = acc[mi][ni][3];
            if (round_out) { o0 = rnd(o0); o1 = rnd(o1); o2 = rnd(o2); o3 = rnd(o3); }
            if (bias) {
                float b0 = bias[col], b1 = bias[col + 1];
                o0 += b0; o1 += b1; o2 += b0; o3 += b1;
            }
            *(float2*)(C + (size_t)row * N + col) = make_float2(o0, o1);
            *(float2*)(C + (size_t)(row + 8) * N + col) = make_float2(o2, o3);
        }
    }
}

// ---------------------------------------------------------------------------
// RMSNorm + RoPE on q and k, in place. Writes tf32-rounded values; q is
// additionally pre-scaled by hd^-0.5 = 0.125 (exact power of 2).
// ---------------------------------------------------------------------------
__global__ void __launch_bounds__(512) rmsrope_kernel(
    float* __restrict__ qkv,
    const float* __restrict__ rc, const float* __restrict__ rs,
    const float* __restrict__ qw, const float* __restrict__ kw)
{
    const int bn = blockIdx.x;
    const int n = bn & (NSEQ - 1);
    const int h = threadIdx.x >> 5;
    const int lane = threadIdx.x & 31;

    float* q = qkv + (size_t)bn * C3 + h * HD;
    float* k = q + CDIM;
    const int e1 = lane, e2 = lane + 32;

    const float c1 = rc[n * HD + e1], c2 = rc[n * HD + e2];
    const float s1 = rs[n * HD + e1], s2 = rs[n * HD + e2];

    {
        float a = q[e1], b = q[e2];
        float ss = a * a + b * b;
#pragma unroll
        for (int m = 16; m > 0; m >>= 1) ss += __shfl_xor_sync(0xffffffffu, ss, m);
        float inv = rsqrtf(ss * (1.0f / HD) + 1e-6f);
        a *= inv * qw[e1];
        b *= inv * qw[e2];
        q[e1] = rnd((a * c1 - b * s1) * 0.125f);
        q[e2] = rnd((b * c2 + a * s2) * 0.125f);
    }
    {
        float a = k[e1], b = k[e2];
        float ss = a * a + b * b;
#pragma unroll
        for (int m = 16; m > 0; m >>= 1) ss += __shfl_xor_sync(0xffffffffu, ss, m);
        float inv = rsqrtf(ss * (1.0f / HD) + 1e-6f);
        a *= inv * kw[e1];
        b *= inv * kw[e2];
        k[e1] = rnd(a * c1 - b * s1);
        k[e2] = rnd(b * c2 + a * s2);
    }
}

// ---------------------------------------------------------------------------
// Tensor-core flash attention, cp.async 2-stage K/V pipeline (unchanged).
// smem: Ks[2][64][68], Vs[2][64][72], Ps[128][68] = 106496 B dynamic.
// ---------------------------------------------------------------------------
#define KS_STRIDE 68
#define VS_STRIDE 72
#define PS_STRIDE 68

__global__ void __launch_bounds__(256) attn_mma_kernel(
    const float* __restrict__ qkv, float* __restrict__ out)
{
    extern __shared__ float sm[];
    float* Ks = sm;                          // [2][64][68]
    float* Vs = sm + 2 * 64 * KS_STRIDE;     // [2][64][72]
    float* Ps = Vs + 2 * 64 * VS_STRIDE;     // [128][68]

    const int qb = blockIdx.x, h = blockIdx.y, b = blockIdx.z;
    const int t = threadIdx.x;
    const int wid = t >> 5, lane = t & 31;
    const int r = lane >> 2, c = lane & 3;
    const int mr = wid << 4;

    const size_t base = (size_t)b * NSEQ * C3 + h * HD;

    // ---- Prologue: async-load Q into Ps, then K/V tile 0 into stage 0 ----
#pragma unroll
    for (int i = 0; i < 8; i++) {
        int idx = t + (i << 8);
        int row = idx >> 4;
        int d4  = (idx & 15) << 2;
        cp16(smem_u32(&Ps[row * PS_STRIDE + d4]),
             qkv + base + (size_t)(qb * 128 + row) * C3 + d4);
    }
    cp_commit();

    auto issue_kv = [&](int kt, int s) {
        float* ks = Ks + s * 64 * KS_STRIDE;
        float* vs = Vs + s * 64 * VS_STRIDE;
#pragma unroll
        for (int i = 0; i < 4; i++) {
            int idx = t + (i << 8);
            int row = idx >> 4;
            int d4  = (idx & 15) << 2;
            const float* src = qkv + base + (size_t)(kt * 64 + row) * C3 + d4;
            cp16(smem_u32(&ks[row * KS_STRIDE + d4]), src + CDIM);
            cp16(smem_u32(&vs[row * VS_STRIDE + d4]), src + 2 * CDIM);
        }
        cp_commit();
    };
    issue_kv(0, 0);

    cp_wait<1>();          // Q complete (tile 0 may still be in flight)
    __syncthreads();

    uint32_t qa[8][4];
#pragma unroll
    for (int kk = 0; kk < 8; kk++) {
        int k8 = kk << 3;
        qa[kk][0] = __float_as_uint(Ps[(mr + r    ) * PS_STRIDE + k8 + c    ]);
        qa[kk][1] = __float_as_uint(Ps[(mr + r + 8) * PS_STRIDE + k8 + c    ]);
        qa[kk][2] = __float_as_uint(Ps[(mr + r    ) * PS_STRIDE + k8 + c + 4]);
        qa[kk][3] = __float_as_uint(Ps[(mr + r + 8) * PS_STRIDE + k8 + c + 4]);
    }

    float oacc[8][4] = {};
    float m0 = -1e30f, m1 = -1e30f;
    float l0 = 0.0f,   l1 = 0.0f;
    int s = 0;

    for (int kt = 0; kt < NSEQ / 64; kt++) {
        if (kt + 1 < NSEQ / 64) { issue_kv(kt + 1, s ^ 1); cp_wait<1>(); }
        else                    { cp_wait<0>(); }
        __syncthreads();

        const float* ks = Ks + s * 64 * KS_STRIDE;
        const float* vs = Vs + s * 64 * VS_STRIDE;

        // ---- S = Q K^T ----
        float sacc[8][4] = {};
#pragma unroll
        for (int kk = 0; kk < 8; kk++) {
            int k8 = kk << 3;
            uint32_t bf[8][2];
#pragma unroll
            for (int ni = 0; ni < 8; ni++) {
                bf[ni][0] = __float_as_uint(ks[(ni * 8 + r) * KS_STRIDE + k8 + c    ]);
                bf[ni][1] = __float_as_uint(ks[(ni * 8 + r) * KS_STRIDE + k8 + c + 4]);
            }
#pragma unroll
            for (int ni = 0; ni < 8; ni++)
                mma_tf32(sacc[ni], qa[kk], bf[ni]);
        }

        // ---- Online softmax ----
        float mx0 = -1e30f, mx1 = -1e30f;
#pragma unroll
        for (int ni = 0; ni < 8; ni++) {
            mx0 = fmaxf(mx0, fmaxf(sacc[ni][0], sacc[ni][1]));
            mx1 = fmaxf(mx1, fmaxf(sacc[ni][2], sacc[ni][3]));
        }
        mx0 = fmaxf(mx0, __shfl_xor_sync(0xffffffffu, mx0, 1));
        mx0 = fmaxf(mx0, __shfl_xor_sync(0xffffffffu, mx0, 2));
        mx1 = fmaxf(mx1, __shfl_xor_sync(0xffffffffu, mx1, 1));
        mx1 = fmaxf(mx1, __shfl_xor_sync(0xffffffffu, mx1, 2));

        float mn0 = fmaxf(m0, mx0), mn1 = fmaxf(m1, mx1);
        float al0 = __expf(m0 - mn0), al1 = __expf(m1 - mn1);
        m0 = mn0; m1 = mn1;

        float sum0 = 0.0f, sum1 = 0.0f;
#pragma unroll
        for (int ni = 0; ni < 8; ni++) {
            float p0 = __expf(sacc[ni][0] - mn0);
            float p1 = __expf(sacc[ni][1] - mn0);
            float p2 = __expf(sacc[ni][2] - mn1);
            float p3 = __expf(sacc[ni][3] - mn1);
            sum0 += p0 + p1; sum1 += p2 + p3;
            int col = (ni << 3) + (c << 1);
            float2 w0 = make_float2(rnd(p0), rnd(p1));
            float2 w1 = make_float2(rnd(p2), rnd(p3));
            *(float2*)&Ps[(mr + r    ) * PS_STRIDE + col] = w0;
            *(float2*)&Ps[(mr + r + 8) * PS_STRIDE + col] = w1;
        }
        sum0 += __shfl_xor_sync(0xffffffffu, sum0, 1);
        sum0 += __shfl_xor_sync(0xffffffffu, sum0, 2);
        sum1 += __shfl_xor_sync(0xffffffffu, sum1, 1);
        sum1 += __shfl_xor_sync(0xffffffffu, sum1, 2);
        l0 = l0 * al0 + sum0;
        l1 = l1 * al1 + sum1;

#pragma unroll
        for (int ni = 0; ni < 8; ni++) {
            oacc[ni][0] *= al0; oacc[ni][1] *= al0;
            oacc[ni][2] *= al1; oacc[ni][3] *= al1;
        }
        __syncwarp();   // P slab is intra-warp

        // ---- O += P V ----
#pragma unroll
        for (int kk = 0; kk < 8; kk++) {
            int k8 = kk << 3;
            uint32_t pa[4];
            pa[0] = __float_as_uint(Ps[(mr + r    ) * PS_STRIDE + k8 + c    ]);
            pa[1] = __float_as_uint(Ps[(mr + r + 8) * PS_STRIDE + k8 + c    ]);
            pa[2] = __float_as_uint(Ps[(mr + r    ) * PS_STRIDE + k8 + c + 4]);
            pa[3] = __float_as_uint(Ps[(mr + r + 8) * PS_STRIDE + k8 + c + 4]);
            uint32_t bf[8][2];
#pragma unroll
            for (int ni = 0; ni < 8; ni++) {
                bf[ni][0] = __float_as_uint(vs[(k8 + c    ) * VS_STRIDE + (ni << 3) + r]);
                bf[ni][1] = __float_as_uint(vs[(k8 + c + 4) * VS_STRIDE + (ni << 3) + r]);
            }
#pragma unroll
            for (int ni = 0; ni < 8; ni++)
                mma_tf32(oacc[ni], pa, bf[ni]);
        }
        __syncthreads();   // all reads of this stage done before it is refilled
        s ^= 1;
    }

    // ---- Epilogue: normalize, tf32-round, write [B,N,C] ----
    const size_t obase = (size_t)b * NSEQ * CDIM + h * HD;
    const float invl0 = 1.0f / l0, invl1 = 1.0f / l1;
    const int row0 = qb * 128 + mr + r;
#pragma unroll
    for (int ni = 0; ni < 8; ni++) {
        int col = (ni << 3) + (c << 1);
        float2 w0 = make_float2(rnd(oacc[ni][0] * invl0), rnd(oacc[ni][1] * invl0));
        float2 w1 = make_float2(rnd(oacc[ni][2] * invl1), rnd(oacc[ni][3] * invl1));
        *(float2*)(out + obase + (size_t)row0 * CDIM + col) = w0;
        *(float2*)(out + obase + (size_t)(row0 + 8) * CDIM + col) = w1;
    }
}

// ---------------------------------------------------------------------------
extern "C" void kernel_launch(void* const* d_in, const int* in_sizes, int n_in,
                              void* d_out, int out_size)
{
    const float* x     = (const float*)d_in[0];
    const float* rc    = (const float*)d_in[1];
    const float* rs    = (const float*)d_in[2];
    const float* wqkv  = (const float*)d_in[3];
    const float* wproj = (const float*)d_in[4];
    const float* bproj = (const float*)d_in[5];
    const float* qw    = (const float*)d_in[6];
    const float* kw    = (const float*)d_in[7];
    float* out = (float*)d_out;

    float *qkv, *attn, *xr, *wqkvr, *wprojr;
    cudaGetSymbolAddress((void**)&qkv, g_qkv);
    cudaGetSymbolAddress((void**)&attn, g_attn);
    cudaGetSymbolAddress((void**)&xr, g_xr);
    cudaGetSymbolAddress((void**)&wqkvr, g_wqkvr);
    cudaGetSymbolAddress((void**)&wprojr, g_wprojr);

    const int M = BATCH * NSEQ; // 8192
    const int GEMM_SMEM = 2 * 2 * 128 * 36 * 4;                                   // 73728
    const int ATTN_SMEM = (2 * 64 * KS_STRIDE + 2 * 64 * VS_STRIDE + 128 * PS_STRIDE) * 4; // 106496

    cudaFuncSetAttribute(gemm_tf32_cp, cudaFuncAttributeMaxDynamicSharedMemorySize, GEMM_SMEM);
    cudaFuncSetAttribute(attn_mma_kernel, cudaFuncAttributeMaxDynamicSharedMemorySize, ATTN_SMEM);

    // 0) Round inputs to tf32-valid fp32
    {
        int n4x = M * CDIM / 4;          // 2097152
        int n4q = C3 * CDIM / 4;         // 786432
        int n4p = CDIM * CDIM / 4;       // 262144
        round_tf32_kernel<<<(n4x + 255) / 256, 256>>>((const float4*)x, (float4*)xr, n4x);
        round_tf32_kernel<<<(n4q + 255) / 256, 256>>>((const float4*)wqkv, (float4*)wqkvr, n4q);
        round_tf32_kernel<<<(n4p + 255) / 256, 256>>>((const float4*)wproj, (float4*)wprojr, n4p);
    }

    // 1) QKV projection (output tf32-rounded so attention can raw-copy V)
    gemm_tf32_cp<<<dim3(C3 / 128, M / 128), 256, GEMM_SMEM>>>(
        xr, wqkvr, nullptr, qkv, M, C3, CDIM, 1);

    // 2) RMSNorm + RoPE in place (writes tf32-rounded q*0.125, k)
    rmsrope_kernel<<<M, 512>>>(qkv, rc, rs, qw, kw);

    // 3) Flash attention (cp.async pipelined; output tf32-rounded)
    attn_mma_kernel<<<dim3(NSEQ / 128, HNUM, BATCH), 256, ATTN_SMEM>>>(qkv, attn);

    // 4) Output projection + bias
    gemm_tf32_cp<<<dim3(CDIM / 128, M / 128), 256, GEMM_SMEM>>>(
        attn, wprojr, bproj, out, M, CDIM, CDIM, 0);
}